// round 15
// baseline (speedup 1.0000x reference)
#include <cuda_runtime.h>
#include <cuda_fp16.h>
#include <math.h>

typedef unsigned int        u32;
typedef unsigned long long  u64;

#define HW     (512*512)
#define NB     4
#define NC     64
#define HID    128
#define NK     16
#define SOFTEN 10000.0f
#define EPSV   1e-8f

#define TILE        128
#define NTILES      (NB * HW / TILE)   // 8192
#define NCTA        296                // 2 CTAs per SM
#define THREADS     256

// out layout: transformed_img [4,3,512,512] | m [4,16,512,512] | palette [4,16,3,1,1]
#define OFF_T  ((size_t)0)
#define OFF_M  ((size_t)NB * 3 * HW)
#define OFF_P  (OFF_M + (size_t)NB * NK * HW)

// ---- dynamic smem layout (bytes), total 98560 (2 CTAs: 197120 < 228KB) ----
#define SM_AH     0                      // 32 c2-rows x 136 u32 = 17408
#define SM_AL     17408                  // 17408
#define SM_W1F    34816                  // 4ks x 16nb x 32 lane x uint4 = 32768
#define SM_W2KP   67584                  // 128 o x 10 u64 (8 k-pairs + pad) = 10240
#define SM_SLB    77824                  // 2nw x 128px x 20 f32 = 20480 (80B rows: aligned)
#define SM_SNUM   98304                  // 192
#define SM_SDEN   98496                  // 64
#define SMEM_BYTES 98560

// ---- scratch (no allocations allowed) ----
__device__ float         gNum[NB * NK * 3];
__device__ float         gDen[NB * NK];
__device__ float         gPal[NB * NK * 3];
__device__ unsigned char gArg[NB * HW];

// fp16 m16n8k16 HMMA, f32 accumulate
__device__ __forceinline__ void mma16(float d[4], u32 a0, u32 a1, u32 a2, u32 a3,
                                      u32 b0, u32 b1) {
    asm volatile(
        "mma.sync.aligned.m16n8k16.row.col.f32.f16.f16.f32 "
        "{%0,%1,%2,%3},{%4,%5,%6,%7},{%8,%9},{%0,%1,%2,%3};"
        : "+f"(d[0]), "+f"(d[1]), "+f"(d[2]), "+f"(d[3])
        : "r"(a0), "r"(a1), "r"(a2), "r"(a3), "r"(b0), "r"(b1));
}

// exact 2-way fp16 split of a float pair: (x,y) -> hi fp16x2 + lo fp16x2
__device__ __forceinline__ void split2(float x, float y, u32& hi, u32& lo) {
    __half2 h = __floats2half2_rn(x, y);
    float2  b = __half22float2(h);
    __half2 l = __floats2half2_rn(x - b.x, y - b.y);
    hi = *(u32*)&h;
    lo = *(u32*)&l;
}

// packed f32x2
__device__ __forceinline__ u64 pack2(float lo, float hi) {
    u64 r; asm("mov.b64 %0, {%1, %2};" : "=l"(r) : "f"(lo), "f"(hi)); return r;
}
__device__ __forceinline__ void unpack2(float& lo, float& hi, u64 v) {
    asm("mov.b64 {%0, %1}, %2;" : "=f"(lo), "=f"(hi) : "l"(v));
}
#define FMA2(d, a, b, c) \
    asm("fma.rn.f32x2 %0, %1, %2, %3;" : "=l"(d) : "l"(a), "l"(b), "l"(c))

__global__ void zero_kernel() {
    int t = threadIdx.x;
    if (t < NB * NK * 3) gNum[t] = 0.0f;
    if (t < NB * NK)     gDen[t] = 0.0f;
}

// ======================= main kernel: 2 CTAs per SM =========================
__global__ __launch_bounds__(THREADS, 2) void main_kernel(
    const float* __restrict__ img,
    const float* __restrict__ feat,
    const float* __restrict__ b1,
    const float* __restrict__ W1,
    const float* __restrict__ W2,
    float* __restrict__ out)
{
    extern __shared__ char sm[];
    const int tid = threadIdx.x;
    const int wid = tid >> 5;
    const int lid = tid & 31;
    const int mwarp = wid & 3;        // px range: mwarp*32 .. +31
    const int nwarp = wid >> 2;       // o range:  nwarp*64 .. +63
    const int lq = lid & 3;
    const int lg = lid >> 2;

    if (tid < NK * 3) *(float*)(sm + SM_SNUM + tid * 4) = 0.0f;
    if (tid < NK)     *(float*)(sm + SM_SDEN + tid * 4) = 0.0f;

    // ---- stage W1 fragments + W2 k-pair table (once per CTA) ----
    {
        uint4* W1F = (uint4*)(sm + SM_W1F);
        for (int e = tid; e < 4 * 16 * 32; e += THREADS) {
            int ks = e >> 9, nb = (e >> 5) & 15, ln = e & 31;
            int o  = nb * 8 + (ln >> 2);
            int c0 = ks * 16 + 2 * (ln & 3);
            u32 b0h, b0l, b1h, b1l;
            split2(W1[o * NC + c0],     W1[o * NC + c0 + 1], b0h, b0l);
            split2(W1[o * NC + c0 + 8], W1[o * NC + c0 + 9], b1h, b1l);
            W1F[e] = make_uint4(b0h, b1h, b0l, b1l);
        }
        // W2kp[o][q] = (W2[2q][o], W2[2q+1][o]); row stride 10 u64 = 80B (16B aligned)
        u64* W2KP = (u64*)(sm + SM_W2KP);
        for (int i = tid; i < HID * 8; i += THREADS) {
            int o = i >> 3, q = i & 7;
            W2KP[o * 10 + q] = pack2(W2[(2 * q) * HID + o], W2[(2 * q + 1) * HID + o]);
        }
    }
    __syncthreads();

    const uint4* W1F  = (const uint4*)(sm + SM_W1F);
    const char*  W2KP = sm + SM_W2KP;
    u32* AH = (u32*)(sm + SM_AH);
    u32* AL = (u32*)(sm + SM_AL);
    float* slb  = (float*)(sm + SM_SLB);
    float* snum = (float*)(sm + SM_SNUM);
    float* sden = (float*)(sm + SM_SDEN);

    for (int t = blockIdx.x; t < NTILES; t += NCTA) {
        const int bb = t >> 11;
        const int p0 = (t & 2047) * TILE;

        // ---- load + split feat tile: LDG -> fp16 split -> STS (AH/AL) ----
        {
            const float* fb = feat + (size_t)bb * NC * HW + p0;
#pragma unroll
            for (int r = 0; r < 4; r++) {
                int idx = tid + THREADS * r;       // 1024 = 32 c2 x 32 px4
                int c2 = idx >> 5, px4 = idx & 31;
                float4 f0 = *(const float4*)(fb + (size_t)(2 * c2)     * HW + px4 * 4);
                float4 f1 = *(const float4*)(fb + (size_t)(2 * c2 + 1) * HW + px4 * 4);
                uint4 hi, lo;
                split2(f0.x, f1.x, hi.x, lo.x);
                split2(f0.y, f1.y, hi.y, lo.y);
                split2(f0.z, f1.z, hi.z, lo.z);
                split2(f0.w, f1.w, hi.w, lo.w);
                *(uint4*)(AH + c2 * 136 + px4 * 4) = hi;
                *(uint4*)(AL + c2 * 136 + px4 * 4) = lo;
            }
        }
        __syncthreads();

        // ================= GEMM1 (tensor): h = feat * W1^T, fp16 3-term ==========
        float d[2][8][4];
#pragma unroll
        for (int mb = 0; mb < 2; mb++)
#pragma unroll
            for (int j = 0; j < 8; j++)
#pragma unroll
                for (int r = 0; r < 4; r++) d[mb][j][r] = 0.0f;

#pragma unroll
        for (int ks = 0; ks < 4; ks++) {
            u32 ah[2][4], al[2][4];
#pragma unroll
            for (int mb = 0; mb < 2; mb++) {
                const int pxr = mwarp * 32 + mb * 16 + lg;
                const int c2  = ks * 8 + lq;
                ah[mb][0] = AH[c2 * 136 + pxr];
                ah[mb][1] = AH[c2 * 136 + pxr + 8];
                ah[mb][2] = AH[(c2 + 4) * 136 + pxr];
                ah[mb][3] = AH[(c2 + 4) * 136 + pxr + 8];
                al[mb][0] = AL[c2 * 136 + pxr];
                al[mb][1] = AL[c2 * 136 + pxr + 8];
                al[mb][2] = AL[(c2 + 4) * 136 + pxr];
                al[mb][3] = AL[(c2 + 4) * 136 + pxr + 8];
            }
#pragma unroll
            for (int j = 0; j < 8; j++) {
                uint4 bq = W1F[(ks * 16 + nwarp * 8 + j) * 32 + lid];
#pragma unroll
                for (int mb = 0; mb < 2; mb++) {
                    mma16(d[mb][j], ah[mb][0], ah[mb][1], ah[mb][2], ah[mb][3], bq.x, bq.y);
                    mma16(d[mb][j], ah[mb][0], ah[mb][1], ah[mb][2], ah[mb][3], bq.z, bq.w);
                    mma16(d[mb][j], al[mb][0], al[mb][1], al[mb][2], al[mb][3], bq.x, bq.y);
                }
            }
        }

        // ========== GEMV2 on fma pipe (exact fp32): logits = relu(d+b1) * W2^T ====
        // Two k-half passes (kk=0: k0..7, kk=1: k8..15) to bound register pressure.
#pragma unroll
        for (int kk = 0; kk < 2; kk++) {
            u64 lp2[4][4];                 // [row = mb*2+half][q-pair]
#pragma unroll
            for (int r = 0; r < 4; r++)
#pragma unroll
                for (int q = 0; q < 4; q++) lp2[r][q] = 0ULL;

#pragma unroll
            for (int j = 0; j < 8; j++) {
                const int o0 = nwarp * 64 + j * 8 + 2 * lq;     // and o0+1
                float2 bj = *(const float2*)(b1 + o0);
                const ulonglong2* w0p = (const ulonglong2*)(W2KP + (size_t)o0 * 80 + kk * 32);
                const ulonglong2* w1p = (const ulonglong2*)(W2KP + (size_t)(o0 + 1) * 80 + kk * 32);
                ulonglong2 w0a = w0p[0], w0b = w0p[1];
                ulonglong2 w1a = w1p[0], w1b = w1p[1];
#pragma unroll
                for (int mb = 0; mb < 2; mb++)
#pragma unroll
                    for (int half = 0; half < 2; half++) {
                        const int row = mb * 2 + half;
                        float h0 = fmaxf(d[mb][j][half * 2 + 0] + bj.x, 0.0f);
                        float h1 = fmaxf(d[mb][j][half * 2 + 1] + bj.y, 0.0f);
                        u64 hp0 = pack2(h0, h0);
                        u64 hp1 = pack2(h1, h1);
                        FMA2(lp2[row][0], hp0, w0a.x, lp2[row][0]);
                        FMA2(lp2[row][1], hp0, w0a.y, lp2[row][1]);
                        FMA2(lp2[row][2], hp0, w0b.x, lp2[row][2]);
                        FMA2(lp2[row][3], hp0, w0b.y, lp2[row][3]);
                        FMA2(lp2[row][0], hp1, w1a.x, lp2[row][0]);
                        FMA2(lp2[row][1], hp1, w1a.y, lp2[row][1]);
                        FMA2(lp2[row][2], hp1, w1b.x, lp2[row][2]);
                        FMA2(lp2[row][3], hp1, w1b.y, lp2[row][3]);
                    }
            }

            // reduce across the lq quad (lanes xor 1, 2): packed fp32 adds
#pragma unroll
            for (int r = 0; r < 4; r++)
#pragma unroll
                for (int q = 0; q < 4; q++) {
                    float a0, a1, s0, s1;
                    u64 v = lp2[r][q];
                    u64 vx = __shfl_xor_sync(0xffffffffu, v, 1);
                    unpack2(a0, a1, v); unpack2(s0, s1, vx);
                    a0 += s0; a1 += s1;
                    v = pack2(a0, a1);
                    vx = __shfl_xor_sync(0xffffffffu, v, 2);
                    unpack2(a0, a1, v); unpack2(s0, s1, vx);
                    lp2[r][q] = pack2(a0 + s0, a1 + s1);
                }

            // lq==0 lanes write this k-half's partial logits (8 floats per row)
            if (lq == 0) {
#pragma unroll
                for (int mb = 0; mb < 2; mb++)
#pragma unroll
                    for (int half = 0; half < 2; half++) {
                        const int row = mb * 2 + half;
                        const int px = mwarp * 32 + mb * 16 + half * 8 + lg;
                        float f0, f1, f2, f3, f4, f5, f6, f7;
                        unpack2(f0, f1, lp2[row][0]);
                        unpack2(f2, f3, lp2[row][1]);
                        unpack2(f4, f5, lp2[row][2]);
                        unpack2(f6, f7, lp2[row][3]);
                        float* dst = &slb[(nwarp * 128 + px) * 20 + kk * 8];
                        *(float4*)(dst)     = make_float4(f0, f1, f2, f3);
                        *(float4*)(dst + 4) = make_float4(f4, f5, f6, f7);
                    }
            }
        }
        __syncthreads();

        // ================= epilogue: 2 lanes per pixel =============================
        {
            const int pxl = wid * 16 + (lid & 15);
            const int kh  = lid >> 4;              // k-half: 0 -> k 0..7, 1 -> 8..15
            const int p   = p0 + pxl;

            float4 vA0 = *(float4*)&slb[pxl * 20 + kh * 8];
            float4 vA1 = *(float4*)&slb[pxl * 20 + kh * 8 + 4];
            float4 vB0 = *(float4*)&slb[(128 + pxl) * 20 + kh * 8];
            float4 vB1 = *(float4*)&slb[(128 + pxl) * 20 + kh * 8 + 4];
            float v[8] = {vA0.x + vB0.x, vA0.y + vB0.y, vA0.z + vB0.z, vA0.w + vB0.w,
                          vA1.x + vB1.x, vA1.y + vB1.y, vA1.z + vB1.z, vA1.w + vB1.w};

            float mx = v[0];
            int   am = kh * 8;
#pragma unroll
            for (int k = 1; k < 8; k++)
                if (v[k] > mx) { mx = v[k]; am = kh * 8 + k; }

            float mo_ = __shfl_xor_sync(0xffffffffu, mx, 16);
            int   ao_ = __shfl_xor_sync(0xffffffffu, am, 16);
            bool take = (mo_ > mx) || (mo_ == mx && ao_ < am);
            float gmax = take ? mo_ : mx;
            int   gam  = take ? ao_ : am;

            float e[8], s = 0.0f;
#pragma unroll
            for (int k = 0; k < 8; k++) { e[k] = __expf(SOFTEN * (v[k] - gmax)); s += e[k]; }
            s += __shfl_xor_sync(0xffffffffu, s, 16);
            const float inv = 1.0f / s;

            float* mo = out + OFF_M + (size_t)bb * NK * HW + (size_t)kh * 8 * HW + p;
#pragma unroll
            for (int k = 0; k < 8; k++) mo[(size_t)k * HW] = e[k] * inv;

            if (kh == 0) {
                gArg[(size_t)bb * HW + p] = (unsigned char)gam;
                const float* ip = img + (size_t)bb * 3 * HW + p;
                atomicAdd(&snum[gam * 3 + 0], __ldg(ip));
                atomicAdd(&snum[gam * 3 + 1], __ldg(ip + HW));
                atomicAdd(&snum[gam * 3 + 2], __ldg(ip + 2 * HW));
                atomicAdd(&sden[gam], 1.0f);
            }
        }
        __syncthreads();
        if (tid < NK * 3) {
            atomicAdd(&gNum[bb * NK * 3 + tid], snum[tid]);
            snum[tid] = 0.0f;
        }
        if (tid < NK) {
            atomicAdd(&gDen[bb * NK + tid], sden[tid]);
            sden[tid] = 0.0f;
        }
        __syncthreads();   // snum/sden reset + AH/AL/slb reuse ordered before next tile
    }
}

__global__ void palette_kernel(float* __restrict__ out) {
    int t = threadIdx.x;
    if (t < NB * NK) {
        float d = gDen[t] + EPSV;
#pragma unroll
        for (int c = 0; c < 3; c++) {
            float v = gNum[t * 3 + c] / d;
            gPal[t * 3 + c] = v;
            out[OFF_P + (size_t)t * 3 + c] = v;
        }
    }
}

__global__ __launch_bounds__(256) void transform_kernel(float* __restrict__ out) {
    __shared__ float pal[NB * NK * 3];
    int t = threadIdx.x;
    if (t < NB * NK * 3) pal[t] = gPal[t];
    __syncthreads();

    int g = blockIdx.x * 256 + t;
    int b = g / HW;
    int p = g % HW;
    int am = gArg[g];

    const float* pp = &pal[(b * NK + am) * 3];
    float* op = out + OFF_T + (size_t)b * 3 * HW + p;
    op[0]              = pp[0];
    op[(size_t)HW]     = pp[1];
    op[(size_t)2 * HW] = pp[2];
}

extern "C" void kernel_launch(void* const* d_in, const int* in_sizes, int n_in,
                              void* d_out, int out_size) {
    const float* img  = (const float*)d_in[0];
    const float* feat = (const float*)d_in[1];
    const float* W1   = (const float*)d_in[2];
    const float* b1   = (const float*)d_in[3];
    const float* W2   = (const float*)d_in[4];
    float* out = (float*)d_out;

    cudaFuncSetAttribute(main_kernel, cudaFuncAttributeMaxDynamicSharedMemorySize, SMEM_BYTES);

    zero_kernel<<<1, 256>>>();
    main_kernel<<<NCTA, THREADS, SMEM_BYTES>>>(img, feat, b1, W1, W2, out);
    palette_kernel<<<1, 64>>>(out);
    transform_kernel<<<NB * HW / 256, 256>>>(out);
}

// round 17
// speedup vs baseline: 1.2842x; 1.2842x over previous
#include <cuda_runtime.h>
#include <cuda_fp16.h>
#include <math.h>

typedef unsigned int        u32;
typedef unsigned long long  u64;

#define HW     (512*512)
#define NB     4
#define NC     64
#define HID    128
#define NK     16
#define SOFTEN 10000.0f
#define EPSV   1e-8f

#define TILE        128
#define NTILES      (NB * HW / TILE)   // 8192
#define NCTA        296                // 2 CTAs per SM
#define THREADS     256

// out layout: transformed_img [4,3,512,512] | m [4,16,512,512] | palette [4,16,3,1,1]
#define OFF_T  ((size_t)0)
#define OFF_M  ((size_t)NB * 3 * HW)
#define OFF_P  (OFF_M + (size_t)NB * NK * HW)

// ---- dynamic smem layout (bytes), total 96512 (2 CTAs: 193024 < 228KB) ----
#define SM_AH     0                      // 32 c2-rows x 136 u32 = 17408
#define SM_AL     17408                  // 17408
#define SM_W1F    34816                  // 4ks x 16nb x 32 lane x uint4 = 32768
#define SM_W2F    67584                  // 8ks x 2nb x 32 lane x uint4 = 8192
#define SM_SLB    75776                  // 2nw x 128px x 20 f32 = 20480
#define SM_SNUM   96256                  // 192
#define SM_SDEN   96448                  // 64
#define SMEM_BYTES 96512

// ---- scratch (no allocations allowed) ----
__device__ float         gNum[NB * NK * 3];
__device__ float         gDen[NB * NK];
__device__ unsigned char gArg[NB * HW];

// fp16 m16n8k16 HMMA, f32 accumulate
__device__ __forceinline__ void mma16(float d[4], u32 a0, u32 a1, u32 a2, u32 a3,
                                      u32 b0, u32 b1) {
    asm volatile(
        "mma.sync.aligned.m16n8k16.row.col.f32.f16.f16.f32 "
        "{%0,%1,%2,%3},{%4,%5,%6,%7},{%8,%9},{%0,%1,%2,%3};"
        : "+f"(d[0]), "+f"(d[1]), "+f"(d[2]), "+f"(d[3])
        : "r"(a0), "r"(a1), "r"(a2), "r"(a3), "r"(b0), "r"(b1));
}

// exact 2-way fp16 split of a float pair: (x,y) -> hi fp16x2 + lo fp16x2
__device__ __forceinline__ void split2(float x, float y, u32& hi, u32& lo) {
    __half2 h = __floats2half2_rn(x, y);
    float2  b = __half22float2(h);
    __half2 l = __floats2half2_rn(x - b.x, y - b.y);
    hi = *(u32*)&h;
    lo = *(u32*)&l;
}

__global__ void zero_kernel() {
    int t = threadIdx.x;
    if (t < NB * NK * 3) gNum[t] = 0.0f;
    if (t < NB * NK)     gDen[t] = 0.0f;
}

// ======================= main kernel: 2 CTAs per SM =========================
__global__ __launch_bounds__(THREADS, 2) void main_kernel(
    const float* __restrict__ img,
    const float* __restrict__ feat,
    const float* __restrict__ b1,
    const float* __restrict__ W1,
    const float* __restrict__ W2,
    float* __restrict__ out)
{
    extern __shared__ char sm[];
    const int tid = threadIdx.x;
    const int wid = tid >> 5;
    const int lid = tid & 31;
    const int mwarp = wid & 3;        // px range: mwarp*32 .. +31
    const int nwarp = wid >> 2;       // o range:  nwarp*64 .. +63
    const int lq = lid & 3;
    const int lg = lid >> 2;

    if (tid < NK * 3) *(float*)(sm + SM_SNUM + tid * 4) = 0.0f;
    if (tid < NK)     *(float*)(sm + SM_SDEN + tid * 4) = 0.0f;

    // ---- stage W1/W2 fragments (once per CTA) ----
    {
        uint4* W1F = (uint4*)(sm + SM_W1F);
        for (int e = tid; e < 4 * 16 * 32; e += THREADS) {
            int ks = e >> 9, nb = (e >> 5) & 15, ln = e & 31;
            int o  = nb * 8 + (ln >> 2);
            int c0 = ks * 16 + 2 * (ln & 3);
            u32 b0h, b0l, b1h, b1l;
            split2(W1[o * NC + c0],     W1[o * NC + c0 + 1], b0h, b0l);
            split2(W1[o * NC + c0 + 8], W1[o * NC + c0 + 9], b1h, b1l);
            W1F[e] = make_uint4(b0h, b1h, b0l, b1l);
        }
        uint4* W2F = (uint4*)(sm + SM_W2F);
        for (int e = tid; e < 8 * 2 * 32; e += THREADS) {
            int ks2 = e >> 6, nbk = (e >> 5) & 1, ln = e & 31;
            int cls = nbk * 8 + (ln >> 2);
            int o0  = ks2 * 16 + 2 * (ln & 3);
            u32 b0h, b0l, b1h, b1l;
            split2(W2[cls * HID + o0],     W2[cls * HID + o0 + 1], b0h, b0l);
            split2(W2[cls * HID + o0 + 8], W2[cls * HID + o0 + 9], b1h, b1l);
            W2F[e] = make_uint4(b0h, b1h, b0l, b1l);
        }
    }

    // per-lane bias pairs from GLOBAL b1: o = nwarp*64 + j*8 + 2*lq
    float2 bias2[8];
#pragma unroll
    for (int j = 0; j < 8; j++)
        bias2[j] = *(const float2*)(b1 + nwarp * 64 + j * 8 + 2 * lq);

    __syncthreads();

    const uint4* W1F = (const uint4*)(sm + SM_W1F);
    const uint4* W2F = (const uint4*)(sm + SM_W2F);
    u32* AH = (u32*)(sm + SM_AH);
    u32* AL = (u32*)(sm + SM_AL);
    float* slb  = (float*)(sm + SM_SLB);
    float* snum = (float*)(sm + SM_SNUM);
    float* sden = (float*)(sm + SM_SDEN);

    const int c2_ = tid >> 5;            // prefetch channel-pair base (per r: +8)
    const int px4_ = tid & 31;

    // prologue: prefetch first tile into registers
    float4 pfA[4], pfB[4];
    {
        const int t0 = blockIdx.x;
        const float* fb = feat + (size_t)(t0 >> 11) * NC * HW + (t0 & 2047) * TILE;
#pragma unroll
        for (int r = 0; r < 4; r++) {
            int c2 = c2_ + 8 * r;
            pfA[r] = *(const float4*)(fb + (size_t)(2 * c2)     * HW + px4_ * 4);
            pfB[r] = *(const float4*)(fb + (size_t)(2 * c2 + 1) * HW + px4_ * 4);
        }
    }

    for (int t = blockIdx.x; t < NTILES; t += NCTA) {
        const int bb = t >> 11;
        const int p0 = (t & 2047) * TILE;

        // ---- phase 0: split prefetched regs -> STS (AH/AL) ----
#pragma unroll
        for (int r = 0; r < 4; r++) {
            int c2 = c2_ + 8 * r;
            uint4 hi, lo;
            split2(pfA[r].x, pfB[r].x, hi.x, lo.x);
            split2(pfA[r].y, pfB[r].y, hi.y, lo.y);
            split2(pfA[r].z, pfB[r].z, hi.z, lo.z);
            split2(pfA[r].w, pfB[r].w, hi.w, lo.w);
            *(uint4*)(AH + c2 * 136 + px4_ * 4) = hi;
            *(uint4*)(AL + c2 * 136 + px4_ * 4) = lo;
        }
        __syncthreads();   // sync A

        // ================= GEMM1 (tensor): h = feat * W1^T, fp16 3-term ==========
        float d[2][8][4];
#pragma unroll
        for (int mb = 0; mb < 2; mb++)
#pragma unroll
            for (int j = 0; j < 8; j++)
#pragma unroll
                for (int r = 0; r < 4; r++) d[mb][j][r] = 0.0f;

#pragma unroll
        for (int ks = 0; ks < 4; ks++) {
            u32 ah[2][4], al[2][4];
#pragma unroll
            for (int mb = 0; mb < 2; mb++) {
                const int pxr = mwarp * 32 + mb * 16 + lg;
                const int c2  = ks * 8 + lq;
                ah[mb][0] = AH[c2 * 136 + pxr];
                ah[mb][1] = AH[c2 * 136 + pxr + 8];
                ah[mb][2] = AH[(c2 + 4) * 136 + pxr];
                ah[mb][3] = AH[(c2 + 4) * 136 + pxr + 8];
                al[mb][0] = AL[c2 * 136 + pxr];
                al[mb][1] = AL[c2 * 136 + pxr + 8];
                al[mb][2] = AL[(c2 + 4) * 136 + pxr];
                al[mb][3] = AL[(c2 + 4) * 136 + pxr + 8];
            }
#pragma unroll
            for (int j = 0; j < 8; j++) {
                uint4 bq = W1F[(ks * 16 + nwarp * 8 + j) * 32 + lid];
#pragma unroll
                for (int mb = 0; mb < 2; mb++) {
                    mma16(d[mb][j], ah[mb][0], ah[mb][1], ah[mb][2], ah[mb][3], bq.x, bq.y);
                    mma16(d[mb][j], ah[mb][0], ah[mb][1], ah[mb][2], ah[mb][3], bq.z, bq.w);
                    mma16(d[mb][j], al[mb][0], al[mb][1], al[mb][2], al[mb][3], bq.x, bq.y);
                }
            }
        }

        // ================= GEMM2 (tensor): logits = relu(h+b1) * W2^T =============
        float l2[2][2][4];
#pragma unroll
        for (int mb = 0; mb < 2; mb++)
#pragma unroll
            for (int nbk = 0; nbk < 2; nbk++)
#pragma unroll
                for (int r = 0; r < 4; r++) l2[mb][nbk][r] = 0.0f;

#pragma unroll
        for (int s = 0; s < 4; s++) {
            const int ks2g = nwarp * 4 + s;
#pragma unroll
            for (int mb = 0; mb < 2; mb++) {
                u32 a0h, a0l, a1h, a1l, a2h, a2l, a3h, a3l;
                {
                    const int j = 2 * s;
                    float r0 = fmaxf(d[mb][j][0] + bias2[j].x, 0.0f);
                    float r1 = fmaxf(d[mb][j][1] + bias2[j].y, 0.0f);
                    float r2 = fmaxf(d[mb][j][2] + bias2[j].x, 0.0f);
                    float r3 = fmaxf(d[mb][j][3] + bias2[j].y, 0.0f);
                    split2(r0, r1, a0h, a0l);
                    split2(r2, r3, a1h, a1l);
                }
                {
                    const int j = 2 * s + 1;
                    float r0 = fmaxf(d[mb][j][0] + bias2[j].x, 0.0f);
                    float r1 = fmaxf(d[mb][j][1] + bias2[j].y, 0.0f);
                    float r2 = fmaxf(d[mb][j][2] + bias2[j].x, 0.0f);
                    float r3 = fmaxf(d[mb][j][3] + bias2[j].y, 0.0f);
                    split2(r0, r1, a2h, a2l);
                    split2(r2, r3, a3h, a3l);
                }
#pragma unroll
                for (int nbk = 0; nbk < 2; nbk++) {
                    uint4 w = W2F[(ks2g * 2 + nbk) * 32 + lid];
                    mma16(l2[mb][nbk], a0h, a1h, a2h, a3h, w.x, w.y);
                    mma16(l2[mb][nbk], a0h, a1h, a2h, a3h, w.z, w.w);
                    mma16(l2[mb][nbk], a0l, a1l, a2l, a3l, w.x, w.y);
                }
            }
        }

        // ---- write partial logits (this warp's 64 o) to slb ----
#pragma unroll
        for (int mb = 0; mb < 2; mb++) {
            const int r1 = mwarp * 32 + mb * 16 + lg;
#pragma unroll
            for (int nbk = 0; nbk < 2; nbk++) {
                const int cls = nbk * 8 + 2 * lq;
                *(float2*)&slb[(nwarp * 128 + r1) * 20 + cls] =
                    make_float2(l2[mb][nbk][0], l2[mb][nbk][1]);
                *(float2*)&slb[(nwarp * 128 + r1 + 8) * 20 + cls] =
                    make_float2(l2[mb][nbk][2], l2[mb][nbk][3]);
            }
        }

        // ---- prefetch next tile into registers (d/l2 dead; hides under epilogue) --
        if (t + NCTA < NTILES) {
            const int tn = t + NCTA;
            const float* fb = feat + (size_t)(tn >> 11) * NC * HW + (tn & 2047) * TILE;
#pragma unroll
            for (int r = 0; r < 4; r++) {
                int c2 = c2_ + 8 * r;
                pfA[r] = *(const float4*)(fb + (size_t)(2 * c2)     * HW + px4_ * 4);
                pfB[r] = *(const float4*)(fb + (size_t)(2 * c2 + 1) * HW + px4_ * 4);
            }
        }
        __syncthreads();   // sync B

        // ================= epilogue: 2 lanes per pixel =============================
        {
            const int pxl = wid * 16 + (lid & 15);
            const int kh  = lid >> 4;              // k-half: 0 -> k 0..7, 1 -> 8..15
            const int p   = p0 + pxl;

            float4 vA0 = *(float4*)&slb[pxl * 20 + kh * 8];
            float4 vA1 = *(float4*)&slb[pxl * 20 + kh * 8 + 4];
            float4 vB0 = *(float4*)&slb[(128 + pxl) * 20 + kh * 8];
            float4 vB1 = *(float4*)&slb[(128 + pxl) * 20 + kh * 8 + 4];
            float v[8] = {vA0.x + vB0.x, vA0.y + vB0.y, vA0.z + vB0.z, vA0.w + vB0.w,
                          vA1.x + vB1.x, vA1.y + vB1.y, vA1.z + vB1.z, vA1.w + vB1.w};

            float mx = v[0];
            int   am = kh * 8;
#pragma unroll
            for (int k = 1; k < 8; k++)
                if (v[k] > mx) { mx = v[k]; am = kh * 8 + k; }

            float mo_ = __shfl_xor_sync(0xffffffffu, mx, 16);
            int   ao_ = __shfl_xor_sync(0xffffffffu, am, 16);
            bool take = (mo_ > mx) || (mo_ == mx && ao_ < am);
            float gmax = take ? mo_ : mx;
            int   gam  = take ? ao_ : am;

            float e[8], s = 0.0f;
#pragma unroll
            for (int k = 0; k < 8; k++) { e[k] = __expf(SOFTEN * (v[k] - gmax)); s += e[k]; }
            s += __shfl_xor_sync(0xffffffffu, s, 16);
            const float inv = 1.0f / s;

            float* mo = out + OFF_M + (size_t)bb * NK * HW + (size_t)kh * 8 * HW + p;
#pragma unroll
            for (int k = 0; k < 8; k++) mo[(size_t)k * HW] = e[k] * inv;

            if (kh == 0) {
                gArg[(size_t)bb * HW + p] = (unsigned char)gam;
                const float* ip = img + (size_t)bb * 3 * HW + p;
                atomicAdd(&snum[gam * 3 + 0], __ldg(ip));
                atomicAdd(&snum[gam * 3 + 1], __ldg(ip + HW));
                atomicAdd(&snum[gam * 3 + 2], __ldg(ip + 2 * HW));
                atomicAdd(&sden[gam], 1.0f);
            }
        }
        __syncthreads();   // sync C
        if (tid < NK * 3) {
            atomicAdd(&gNum[bb * NK * 3 + tid], snum[tid]);
            snum[tid] = 0.0f;
        }
        if (tid < NK) {
            atomicAdd(&gDen[bb * NK + tid], sden[tid]);
            sden[tid] = 0.0f;
        }
        // no loop-end sync: reset is separated from next epilogue by syncs A and B;
        // AH/AL and slb write-after-read hazards are covered by syncs B and A.
    }
}

__global__ __launch_bounds__(256) void transform_kernel(float* __restrict__ out) {
    __shared__ float pal[NB * NK * 3];
    int t = threadIdx.x;
    if (t < NB * NK) {
        float dd = gDen[t] + EPSV;
#pragma unroll
        for (int c = 0; c < 3; c++)
            pal[t * 3 + c] = gNum[t * 3 + c] / dd;
    }
    __syncthreads();

    if (blockIdx.x == 0 && t < NB * NK * 3)
        out[OFF_P + t] = pal[t];

    int g = blockIdx.x * 256 + t;
    int b = g / HW;
    int p = g % HW;
    int am = gArg[g];

    const float* pp = &pal[(b * NK + am) * 3];
    float* op = out + OFF_T + (size_t)b * 3 * HW + p;
    op[0]              = pp[0];
    op[(size_t)HW]     = pp[1];
    op[(size_t)2 * HW] = pp[2];
}

extern "C" void kernel_launch(void* const* d_in, const int* in_sizes, int n_in,
                              void* d_out, int out_size) {
    const float* img  = (const float*)d_in[0];
    const float* feat = (const float*)d_in[1];
    const float* W1   = (const float*)d_in[2];
    const float* b1   = (const float*)d_in[3];
    const float* W2   = (const float*)d_in[4];
    float* out = (float*)d_out;

    cudaFuncSetAttribute(main_kernel, cudaFuncAttributeMaxDynamicSharedMemorySize, SMEM_BYTES);

    zero_kernel<<<1, 256>>>();
    main_kernel<<<NCTA, THREADS, SMEM_BYTES>>>(img, feat, b1, W1, W2, out);
    transform_kernel<<<NB * HW / 256, 256>>>(out);
}